// round 4
// baseline (speedup 1.0000x reference)
#include <cuda_runtime.h>

// ---------------------------------------------------------------------------
// ChannelProjection: per-sample LayerNorm over (C,H,W), 1x1-conv MLP
// (64 -> 128 -> SiLU -> 64) on channels [0,64), channel shuffle (groups=2),
// residual add.  z_0: (16,128,192,192) fp32.
//
// Round 3: blocked-GEMM main kernel. Per-pixel version re-read all 64KB of
// weights from smem per pixel (crossbar-bound). Now: 64-pixel tile per block,
// 8px x 8h register tiles, weights amortized over the tile. f32x2 packed FMA.
// ---------------------------------------------------------------------------

#define C_TOT   128
#define CC      64
#define HW      36864            // 192*192
#define NSAMP   16
#define CHW     (C_TOT * HW)
#define NPIX    (NSAMP * HW)
#define RED_BLOCKS  64
#define RED_THREADS 256

#define TPX     64               // pixel tile per block
#define MAIN_THREADS 128
#define BLOCKS_PER_SAMPLE (HW / TPX)   // 576
#define MAIN_GRID (NSAMP * BLOCKS_PER_SAMPLE)  // 9216

__device__ float g_psum[NSAMP * RED_BLOCKS];
__device__ float g_psq [NSAMP * RED_BLOCKS];
__device__ float g_mu  [NSAMP];
__device__ float g_rs  [NSAMP];
__device__ float g_w1T [64 * 128];   // [k][h]
__device__ float g_w2T [128 * 64];   // [h][o]
__device__ float g_b1  [128];
__device__ float g_b2  [64];

typedef unsigned long long u64;

__device__ __forceinline__ u64 pack2(float x, float y) {
    u64 r;
    asm("mov.b64 %0, {%1, %2};" : "=l"(r) : "f"(x), "f"(y));
    return r;
}
__device__ __forceinline__ void unpack2(u64 v, float& x, float& y) {
    asm("mov.b64 {%0, %1}, %2;" : "=f"(x), "=f"(y) : "l"(v));
}
__device__ __forceinline__ u64 ffma2(u64 a, u64 b, u64 c) {
    u64 d;
    asm("fma.rn.f32x2 %0, %1, %2, %3;" : "=l"(d) : "l"(a), "l"(b), "l"(c));
    return d;
}

// ---------------- stage 1: per-sample partial sums (deterministic) ----------
__global__ void cp_stats_kernel(const float* __restrict__ z0) {
    const int b = blockIdx.y;
    const float4* z4 = (const float4*)(z0 + (size_t)b * CHW);
    const int n4 = CHW / 4;

    float s = 0.f, q = 0.f;
    for (int i = blockIdx.x * RED_THREADS + threadIdx.x; i < n4;
         i += RED_BLOCKS * RED_THREADS) {
        float4 v = z4[i];
        s += (v.x + v.y) + (v.z + v.w);
        q += (v.x * v.x + v.y * v.y) + (v.z * v.z + v.w * v.w);
    }
    #pragma unroll
    for (int off = 16; off; off >>= 1) {
        s += __shfl_down_sync(0xffffffffu, s, off);
        q += __shfl_down_sync(0xffffffffu, q, off);
    }
    __shared__ float ss[RED_THREADS / 32], sq[RED_THREADS / 32];
    const int w = threadIdx.x >> 5;
    if ((threadIdx.x & 31) == 0) { ss[w] = s; sq[w] = q; }
    __syncthreads();
    if (threadIdx.x == 0) {
        float S = 0.f, Q = 0.f;
        #pragma unroll
        for (int i = 0; i < RED_THREADS / 32; i++) { S += ss[i]; Q += sq[i]; }
        g_psum[b * RED_BLOCKS + blockIdx.x] = S;
        g_psq [b * RED_BLOCKS + blockIdx.x] = Q;
    }
}

// ---------------- stage 2: finalize mu / rsigma, transpose weights ----------
__global__ void cp_finalize_kernel(const float* __restrict__ w1,
                                   const float* __restrict__ b1,
                                   const float* __restrict__ w2,
                                   const float* __restrict__ b2) {
    const int t = threadIdx.x;   // 128 threads
    if (t < NSAMP) {
        float S = 0.f, Q = 0.f;
        for (int i = 0; i < RED_BLOCKS; i++) {
            S += g_psum[t * RED_BLOCKS + i];
            Q += g_psq [t * RED_BLOCKS + i];
        }
        const float inv_n = 1.f / (float)CHW;
        const float mu  = S * inv_n;
        const float var = Q * inv_n - mu * mu;
        g_mu[t] = mu;
        g_rs[t] = rsqrtf(var + 1e-5f);
    }
    for (int i = t; i < 64 * 128; i += 128) {      // w1T[k][h] = w1[h][k]
        const int k = i >> 7, h = i & 127;
        g_w1T[i] = w1[h * 64 + k];
    }
    for (int i = t; i < 128 * 64; i += 128) {      // w2T[h][o] = w2[o][h]
        const int h = i >> 6, o = i & 63;
        g_w2T[i] = w2[o * 128 + h];
    }
    if (t < 128) g_b1[t] = b1[t];
    if (t < 64)  g_b2[t] = b2[t];
}

// ---------------- stage 3: blocked-GEMM fused main kernel -------------------
// dyn smem: w1T [64][128] f | w2T [128][64] f | union( z [64][64] f , s [128][64] f ) | b1 | b2
#define SMEM_MAIN ((8192 + 8192 + 8192 + 128 + 64) * 4)   // 99072 B

__global__ void __launch_bounds__(MAIN_THREADS)
cp_main_kernel(const float* __restrict__ z0, float* __restrict__ out) {
    extern __shared__ float smem[];
    float* w1s = smem;               // 8192: [k=64][h=128]
    float* w2s = w1s + 8192;         // 8192: [h=128][o=64]
    float* us  = w2s + 8192;         // 8192: z uses first 4096, s uses all
    float* b1s = us + 8192;          // 128
    float* b2s = b1s + 128;          // 64

    const int tid = threadIdx.x;
    const int pg  = tid & 7;         // pixel group: px = pg*8 .. pg*8+7
    const int grp = tid >> 3;        // 0..15: hidden group (GEMM1) / out group (GEMM2)

    const int b  = blockIdx.x / BLOCKS_PER_SAMPLE;
    const int p0 = (blockIdx.x - b * BLOCKS_PER_SAMPLE) * TPX;
    const float* zb = z0 + (size_t)b * CHW;
    float*       ob = out + (size_t)b * CHW;
    const float mu = g_mu[b];
    const float rs = g_rs[b];

    // ---- stage weights + normalized z tile into shared ----
    for (int i = tid; i < 2048; i += MAIN_THREADS)
        ((float4*)w1s)[i] = ((const float4*)g_w1T)[i];
    for (int i = tid; i < 2048; i += MAIN_THREADS)
        ((float4*)w2s)[i] = ((const float4*)g_w2T)[i];
    if (tid < 128) b1s[tid] = g_b1[tid];
    if (tid < 64)  b2s[tid] = g_b2[tid];
    for (int i = tid; i < 64 * TPX; i += MAIN_THREADS) {
        const int c = i >> 6, px = i & 63;
        us[i] = (zb[(size_t)c * HW + p0 + px] - mu) * rs;   // z tile [c][px]
    }
    __syncthreads();

    // ---- GEMM1: h[px][o1] = sum_k z[k][px] * w1T[k][o1], 8px x 8h per thread
    u64 acc1[4][8];
    #pragma unroll
    for (int j = 0; j < 8; j++) {
        const float bv = b1s[grp * 8 + j];
        const u64 d = pack2(bv, bv);
        #pragma unroll
        for (int i = 0; i < 4; i++) acc1[i][j] = d;
    }
    #pragma unroll 8
    for (int k = 0; k < 64; k++) {
        const ulonglong2* zr = (const ulonglong2*)(us + k * 64 + pg * 8);
        const ulonglong2 za = zr[0], zc = zr[1];
        const u64 zp[4] = {za.x, za.y, zc.x, zc.y};
        const float4* wr = (const float4*)(w1s + k * 128 + grp * 8);
        const float4 w0 = wr[0], w1v = wr[1];
        const float wv[8] = {w0.x, w0.y, w0.z, w0.w, w1v.x, w1v.y, w1v.z, w1v.w};
        #pragma unroll
        for (int j = 0; j < 8; j++) {
            const u64 wd = pack2(wv[j], wv[j]);
            #pragma unroll
            for (int i = 0; i < 4; i++) acc1[i][j] = ffma2(zp[i], wd, acc1[i][j]);
        }
    }
    __syncthreads();   // z tile dead; us region becomes s tile

    // ---- SiLU + store s tile [h][px] ----
    #pragma unroll
    for (int j = 0; j < 8; j++) {
        const int h = grp * 8 + j;
        u64 sv[4];
        #pragma unroll
        for (int i = 0; i < 4; i++) {
            float a, c;
            unpack2(acc1[i][j], a, c);
            a = a * (1.f / (1.f + __expf(-a)));
            c = c * (1.f / (1.f + __expf(-c)));
            sv[i] = pack2(a, c);
        }
        ulonglong2* sr = (ulonglong2*)(us + h * 64 + pg * 8);
        ulonglong2 t0; t0.x = sv[0]; t0.y = sv[1];
        ulonglong2 t1; t1.x = sv[2]; t1.y = sv[3];
        sr[0] = t0; sr[1] = t1;
    }
    __syncthreads();

    // ---- GEMM2: y[px][o] = sum_h s[h][px] * w2T[h][o], 8px x 4o per thread
    u64 acc2[4][4];
    #pragma unroll
    for (int j = 0; j < 4; j++) {
        const float bv = b2s[grp * 4 + j];
        const u64 d = pack2(bv, bv);
        #pragma unroll
        for (int i = 0; i < 4; i++) acc2[i][j] = d;
    }
    #pragma unroll 8
    for (int h = 0; h < 128; h++) {
        const ulonglong2* sr = (const ulonglong2*)(us + h * 64 + pg * 8);
        const ulonglong2 sa = sr[0], sc = sr[1];
        const u64 sp[4] = {sa.x, sa.y, sc.x, sc.y};
        const float4 w = *(const float4*)(w2s + h * 64 + grp * 4);
        const float wv[4] = {w.x, w.y, w.z, w.w};
        #pragma unroll
        for (int j = 0; j < 4; j++) {
            const u64 wd = pack2(wv[j], wv[j]);
            #pragma unroll
            for (int i = 0; i < 4; i++) acc2[i][j] = ffma2(sp[i], wd, acc2[i][j]);
        }
    }

    // ---- epilogue: mlp channels -> out[2o] (+residual) ----
    #pragma unroll
    for (int j = 0; j < 4; j++) {
        const int o = grp * 4 + j;
        const size_t row = (size_t)(2 * o) * HW + p0 + pg * 8;
        const float* zr = zb + row;
        float*       orow = ob + row;
        #pragma unroll
        for (int i = 0; i < 4; i++) {
            float a, c;
            unpack2(acc2[i][j], a, c);
            const float2 rv = *(const float2*)(zr + 2 * i);
            float2 ov; ov.x = a + rv.x; ov.y = c + rv.y;
            *(float2*)(orow + 2 * i) = ov;
        }
    }

    // ---- epilogue: z2 channels -> out[2c+1] = (z0[64+c]-mu)*rs + z0[2c+1] ----
    for (int idx = tid; idx < 64 * (TPX / 2); idx += MAIN_THREADS) {
        const int c = idx >> 5;
        const int q = (idx & 31) * 2;
        const float2 zv = *(const float2*)(zb + (size_t)(CC + c) * HW + p0 + q);
        const float2 rv = *(const float2*)(zb + (size_t)(2 * c + 1) * HW + p0 + q);
        float2 ov;
        ov.x = (zv.x - mu) * rs + rv.x;
        ov.y = (zv.y - mu) * rs + rv.y;
        *(float2*)(ob + (size_t)(2 * c + 1) * HW + p0 + q) = ov;
    }
}

// ---------------------------------------------------------------------------
extern "C" void kernel_launch(void* const* d_in, const int* in_sizes, int n_in,
                              void* d_out, int out_size) {
    const float* z0 = (const float*)d_in[0];
    const float* w1 = (const float*)d_in[1];
    const float* b1 = (const float*)d_in[2];
    const float* w2 = (const float*)d_in[3];
    const float* b2 = (const float*)d_in[4];
    float* out = (float*)d_out;

    static bool attr_set = false;
    if (!attr_set) {
        cudaFuncSetAttribute(cp_main_kernel,
                             cudaFuncAttributeMaxDynamicSharedMemorySize,
                             SMEM_MAIN);
        attr_set = true;
    }

    cp_stats_kernel<<<dim3(RED_BLOCKS, NSAMP), RED_THREADS>>>(z0);
    cp_finalize_kernel<<<1, 128>>>(w1, b1, w2, b2);
    cp_main_kernel<<<MAIN_GRID, MAIN_THREADS, SMEM_MAIN>>>(z0, out);
}

// round 5
// speedup vs baseline: 1.1374x; 1.1374x over previous
#include <cuda_runtime.h>

// ---------------------------------------------------------------------------
// ChannelProjection: per-sample LayerNorm over (C,H,W), 1x1-conv MLP
// (64 -> 128 -> SiLU -> 64) on channels [0,64), channel shuffle (groups=2),
// residual add.  z_0: (16,128,192,192) fp32.
//
// Round 4: blocked GEMM, occupancy-fixed.
//   - 256 threads/block, launch_bounds(256,2): 4 warps/SMSP (R3 had only 2).
//   - 4 pixel-tiles per block: weight staging amortized, grid=2304.
//   - SiLU via __fdividef (R1-R3 paid ~20-instr div.rn per evaluation).
//   - f32x2 packed FMA throughout (2 MAC/instr, PTX-only).
// ---------------------------------------------------------------------------

#define C_TOT   128
#define CC      64
#define HW      36864            // 192*192
#define NSAMP   16
#define CHW     (C_TOT * HW)
#define NPIX    (NSAMP * HW)
#define RED_BLOCKS  64
#define RED_THREADS 256

#define TPX     64               // pixels per tile
#define NT      4                // tiles per block
#define MAIN_THREADS 256
#define TILES_PER_SAMPLE (HW / TPX)             // 576 (divisible by NT)
#define MAIN_GRID (NPIX / (TPX * NT))           // 2304

__device__ float g_psum[NSAMP * RED_BLOCKS];
__device__ float g_psq [NSAMP * RED_BLOCKS];
__device__ float g_mu  [NSAMP];
__device__ float g_rs  [NSAMP];
__device__ float g_w1T [64 * 128];   // [k][h]
__device__ float g_w2T [128 * 64];   // [h][o]
__device__ float g_b1  [128];
__device__ float g_b2  [64];

typedef unsigned long long u64;

__device__ __forceinline__ u64 pack2(float x, float y) {
    u64 r;
    asm("mov.b64 %0, {%1, %2};" : "=l"(r) : "f"(x), "f"(y));
    return r;
}
__device__ __forceinline__ void unpack2(u64 v, float& x, float& y) {
    asm("mov.b64 {%0, %1}, %2;" : "=f"(x), "=f"(y) : "l"(v));
}
__device__ __forceinline__ u64 ffma2(u64 a, u64 b, u64 c) {
    u64 d;
    asm("fma.rn.f32x2 %0, %1, %2, %3;" : "=l"(d) : "l"(a), "l"(b), "l"(c));
    return d;
}
__device__ __forceinline__ float silu_fast(float h) {
    return __fdividef(h, 1.f + __expf(-h));
}

// ---------------- stage 1: per-sample partial sums (deterministic) ----------
__global__ void cp_stats_kernel(const float* __restrict__ z0) {
    const int b = blockIdx.y;
    const float4* z4 = (const float4*)(z0 + (size_t)b * CHW);
    const int n4 = CHW / 4;

    float s = 0.f, q = 0.f;
    for (int i = blockIdx.x * RED_THREADS + threadIdx.x; i < n4;
         i += RED_BLOCKS * RED_THREADS) {
        float4 v = z4[i];
        s += (v.x + v.y) + (v.z + v.w);
        q += (v.x * v.x + v.y * v.y) + (v.z * v.z + v.w * v.w);
    }
    #pragma unroll
    for (int off = 16; off; off >>= 1) {
        s += __shfl_down_sync(0xffffffffu, s, off);
        q += __shfl_down_sync(0xffffffffu, q, off);
    }
    __shared__ float ss[RED_THREADS / 32], sq[RED_THREADS / 32];
    const int w = threadIdx.x >> 5;
    if ((threadIdx.x & 31) == 0) { ss[w] = s; sq[w] = q; }
    __syncthreads();
    if (threadIdx.x == 0) {
        float S = 0.f, Q = 0.f;
        #pragma unroll
        for (int i = 0; i < RED_THREADS / 32; i++) { S += ss[i]; Q += sq[i]; }
        g_psum[b * RED_BLOCKS + blockIdx.x] = S;
        g_psq [b * RED_BLOCKS + blockIdx.x] = Q;
    }
}

// ---------------- stage 2: finalize mu / rsigma, transpose weights ----------
__global__ void cp_finalize_kernel(const float* __restrict__ w1,
                                   const float* __restrict__ b1,
                                   const float* __restrict__ w2,
                                   const float* __restrict__ b2) {
    const int t = threadIdx.x;   // 128 threads
    if (t < NSAMP) {
        float S = 0.f, Q = 0.f;
        for (int i = 0; i < RED_BLOCKS; i++) {
            S += g_psum[t * RED_BLOCKS + i];
            Q += g_psq [t * RED_BLOCKS + i];
        }
        const float inv_n = 1.f / (float)CHW;
        const float mu  = S * inv_n;
        const float var = Q * inv_n - mu * mu;
        g_mu[t] = mu;
        g_rs[t] = rsqrtf(var + 1e-5f);
    }
    for (int i = t; i < 64 * 128; i += 128) {      // w1T[k][h] = w1[h][k]
        const int k = i >> 7, h = i & 127;
        g_w1T[i] = w1[h * 64 + k];
    }
    for (int i = t; i < 128 * 64; i += 128) {      // w2T[h][o] = w2[o][h]
        const int h = i >> 6, o = i & 63;
        g_w2T[i] = w2[o * 128 + h];
    }
    if (t < 128) g_b1[t] = b1[t];
    if (t < 64)  g_b2[t] = b2[t];
}

// ---------------- stage 3: blocked-GEMM fused main kernel -------------------
// dyn smem: w1T [64][128] | w2T [128][64] | union( z [64][64], s [128][64] ) | b1 | b2
#define SMEM_MAIN ((8192 + 8192 + 8192 + 128 + 64) * 4)   // 99072 B

__global__ void __launch_bounds__(MAIN_THREADS, 2)
cp_main_kernel(const float* __restrict__ z0, float* __restrict__ out) {
    extern __shared__ float smem[];
    float* w1s = smem;               // [k=64][h=128]
    float* w2s = w1s + 8192;         // [h=128][o=64]
    float* us  = w2s + 8192;         // z: first 4096 floats; s: all 8192
    float* b1s = us + 8192;          // 128
    float* b2s = b1s + 128;          // 64

    const int tid = threadIdx.x;
    const int pg  = tid & 7;         // 8 pixel-groups of 8 px
    const int hg  = tid >> 3;        // 0..31

    const int b      = blockIdx.x / (TILES_PER_SAMPLE / NT);   // /144
    const int p_base = (blockIdx.x % (TILES_PER_SAMPLE / NT)) * (TPX * NT);
    const float* zb = z0 + (size_t)b * CHW;
    float*       ob = out + (size_t)b * CHW;
    const float mu = g_mu[b];
    const float rs = g_rs[b];

    // ---- stage weights once per block ----
    for (int i = tid; i < 2048; i += MAIN_THREADS)
        ((float4*)w1s)[i] = ((const float4*)g_w1T)[i];
    for (int i = tid; i < 2048; i += MAIN_THREADS)
        ((float4*)w2s)[i] = ((const float4*)g_w2T)[i];
    if (tid < 128) b1s[tid] = g_b1[tid];
    if (tid < 64)  b2s[tid] = g_b2[tid];

    for (int t = 0; t < NT; t++) {
        const int p0 = p_base + t * TPX;
        __syncthreads();   // us free (weights staged / prev GEMM2 reads done)

        // ---- normalized z tile [c=64][px=64] ----
        for (int i = tid; i < 1024; i += MAIN_THREADS) {
            const int c = i >> 4, x4 = (i & 15) * 4;
            float4 v = *(const float4*)(zb + (size_t)c * HW + p0 + x4);
            v.x = (v.x - mu) * rs; v.y = (v.y - mu) * rs;
            v.z = (v.z - mu) * rs; v.w = (v.w - mu) * rs;
            *(float4*)(us + c * 64 + x4) = v;
        }
        __syncthreads();

        // ---- GEMM1: 8px x 4h per thread, K=64 ----
        u64 acc1[4][4];
        #pragma unroll
        for (int j = 0; j < 4; j++) {
            const float bv = b1s[hg * 4 + j];
            const u64 d = pack2(bv, bv);
            #pragma unroll
            for (int i = 0; i < 4; i++) acc1[i][j] = d;
        }
        #pragma unroll 4
        for (int k = 0; k < 64; k++) {
            const ulonglong2* zr = (const ulonglong2*)(us + k * 64 + pg * 8);
            const ulonglong2 za = zr[0], zc = zr[1];
            const u64 zp[4] = {za.x, za.y, zc.x, zc.y};
            const float4 w = *(const float4*)(w1s + k * 128 + hg * 4);
            const float wv[4] = {w.x, w.y, w.z, w.w};
            #pragma unroll
            for (int j = 0; j < 4; j++) {
                const u64 wd = pack2(wv[j], wv[j]);
                #pragma unroll
                for (int i = 0; i < 4; i++) acc1[i][j] = ffma2(zp[i], wd, acc1[i][j]);
            }
        }
        __syncthreads();   // z reads done; us becomes s tile

        // ---- SiLU + store s tile [h=128][px=64] ----
        #pragma unroll
        for (int j = 0; j < 4; j++) {
            const int h = hg * 4 + j;
            u64 sv[4];
            #pragma unroll
            for (int i = 0; i < 4; i++) {
                float a, c;
                unpack2(acc1[i][j], a, c);
                sv[i] = pack2(silu_fast(a), silu_fast(c));
            }
            ulonglong2* sr = (ulonglong2*)(us + h * 64 + pg * 8);
            ulonglong2 t0; t0.x = sv[0]; t0.y = sv[1];
            ulonglong2 t1; t1.x = sv[2]; t1.y = sv[3];
            sr[0] = t0; sr[1] = t1;
        }
        __syncthreads();

        // ---- GEMM2: 8px x 2o per thread, K=128 ----
        u64 acc2[4][2];
        #pragma unroll
        for (int j = 0; j < 2; j++) {
            const float bv = b2s[hg * 2 + j];
            const u64 d = pack2(bv, bv);
            #pragma unroll
            for (int i = 0; i < 4; i++) acc2[i][j] = d;
        }
        #pragma unroll 4
        for (int h = 0; h < 128; h++) {
            const ulonglong2* sr = (const ulonglong2*)(us + h * 64 + pg * 8);
            const ulonglong2 sa = sr[0], sc = sr[1];
            const u64 sp[4] = {sa.x, sa.y, sc.x, sc.y};
            const float2 w = *(const float2*)(w2s + h * 64 + hg * 2);
            const u64 w0 = pack2(w.x, w.x);
            const u64 w1d = pack2(w.y, w.y);
            #pragma unroll
            for (int i = 0; i < 4; i++) {
                acc2[i][0] = ffma2(sp[i], w0,  acc2[i][0]);
                acc2[i][1] = ffma2(sp[i], w1d, acc2[i][1]);
            }
        }

        // ---- epilogue: mlp channels -> out[2o] (+residual) ----
        #pragma unroll
        for (int j = 0; j < 2; j++) {
            const int o = hg * 2 + j;
            const size_t row = (size_t)(2 * o) * HW + p0 + pg * 8;
            const float* zr   = zb + row;
            float*       orow = ob + row;
            #pragma unroll
            for (int i = 0; i < 4; i++) {
                float a, c;
                unpack2(acc2[i][j], a, c);
                const float2 rv = *(const float2*)(zr + 2 * i);
                float2 ov; ov.x = a + rv.x; ov.y = c + rv.y;
                *(float2*)(orow + 2 * i) = ov;
            }
        }

        // ---- epilogue: out[2c+1] = (z0[64+c]-mu)*rs + z0[2c+1] ----
        for (int idx = tid; idx < 64 * (TPX / 2); idx += MAIN_THREADS) {
            const int c = idx >> 5;
            const int q = (idx & 31) * 2;
            const float2 zv = *(const float2*)(zb + (size_t)(CC + c) * HW + p0 + q);
            const float2 rv = *(const float2*)(zb + (size_t)(2 * c + 1) * HW + p0 + q);
            float2 ov;
            ov.x = (zv.x - mu) * rs + rv.x;
            ov.y = (zv.y - mu) * rs + rv.y;
            *(float2*)(ob + (size_t)(2 * c + 1) * HW + p0 + q) = ov;
        }
    }
}

// ---------------------------------------------------------------------------
extern "C" void kernel_launch(void* const* d_in, const int* in_sizes, int n_in,
                              void* d_out, int out_size) {
    const float* z0 = (const float*)d_in[0];
    const float* w1 = (const float*)d_in[1];
    const float* b1 = (const float*)d_in[2];
    const float* w2 = (const float*)d_in[3];
    const float* b2 = (const float*)d_in[4];
    float* out = (float*)d_out;

    static bool attr_set = false;
    if (!attr_set) {
        cudaFuncSetAttribute(cp_main_kernel,
                             cudaFuncAttributeMaxDynamicSharedMemorySize,
                             SMEM_MAIN);
        attr_set = true;
    }

    cp_stats_kernel<<<dim3(RED_BLOCKS, NSAMP), RED_THREADS>>>(z0);
    cp_finalize_kernel<<<1, 128>>>(w1, b1, w2, b2);
    cp_main_kernel<<<MAIN_GRID, MAIN_THREADS, SMEM_MAIN>>>(z0, out);
}

// round 7
// speedup vs baseline: 2.8400x; 2.4969x over previous
#include <cuda_runtime.h>
#include <cuda_bf16.h>
#include <cstdint>

// ---------------------------------------------------------------------------
// ChannelProjection via mma.sync (HMMA bf16, base-target ISA — the harness
// compiles PTX for compute_103, so tcgen05/'a'-features are unavailable).
// bf16-split (hi+lo, 3 passes) keeps fp32-level accuracy.
//   k1: per-sample sum/sumsq reduction
//   k2: finalize mu/rsigma + split/pad weights into device arrays
//   k3: per 128-px tile: stage norm z1 -> A hi/lo [px][64k] (pad 72),
//       GEMM1 (m16n8k16, 3 passes) -> SiLU -> S hi/lo [px][128h] (pad 136),
//       GEMM2 -> epilogue (channel shuffle + residual). z2 path in staging.
// ---------------------------------------------------------------------------

#define C_TOT   128
#define CC      64
#define HW      36864
#define NSAMP   16
#define CHW     (C_TOT * HW)
#define NPIX    (NSAMP * HW)
#define RED_BLOCKS  64
#define RED_THREADS 256

#define TPB       4
#define BLOCKS_PER_SAMPLE 72        // 72 * 4 * 128 = 36864 px
#define MAIN_GRID (NSAMP * BLOCKS_PER_SAMPLE)   // 1152

// smem byte offsets (row strides: A/W1 144B (72 bf16), S/W2 272B (136 bf16))
#define OFF_W1HI  0          // [128h][72k]  18432 B
#define OFF_W1LO  18432
#define OFF_W2HI  36864      // [64o][136h]  17408 B
#define OFF_W2LO  54272
#define OFF_AHI   71680      // [128px][72k] 18432 B
#define OFF_ALO   90112
#define OFF_SHI   108544     // [128px][136h] 34816 B (fp32 staging aliases)
#define OFF_SLO   143360
#define OFF_B1    178176     // 128 f32
#define OFF_B2    178688     // 64 f32
#define SMEM_MAIN 178944

__device__ float g_psum[NSAMP * RED_BLOCKS];
__device__ float g_psq [NSAMP * RED_BLOCKS];
__device__ float g_mu  [NSAMP];
__device__ float g_rs  [NSAMP];
__device__ uint4 g_w1hi[1152], g_w1lo[1152];   // 128*72 bf16 padded
__device__ uint4 g_w2hi[1088], g_w2lo[1088];   // 64*136 bf16 padded

// ---------------- helpers ---------------------------------------------------
__device__ __forceinline__ uint32_t smem_u32(const void* p) {
    uint32_t a;
    asm("{ .reg .u64 t; cvta.to.shared.u64 t, %1; cvt.u32.u64 %0, t; }"
        : "=r"(a) : "l"(p));
    return a;
}
__device__ __forceinline__ void ldsm_x4(uint32_t (&r)[4], uint32_t addr) {
    asm volatile("ldmatrix.sync.aligned.m8n8.x4.shared.b16 {%0,%1,%2,%3}, [%4];"
                 : "=r"(r[0]), "=r"(r[1]), "=r"(r[2]), "=r"(r[3]) : "r"(addr));
}
__device__ __forceinline__ void ldsm_x2(uint32_t& r0, uint32_t& r1, uint32_t addr) {
    asm volatile("ldmatrix.sync.aligned.m8n8.x2.shared.b16 {%0,%1}, [%2];"
                 : "=r"(r0), "=r"(r1) : "r"(addr));
}
__device__ __forceinline__ void mma_bf16(float (&c)[4], const uint32_t (&a)[4],
                                         uint32_t b0, uint32_t b1) {
    asm volatile(
        "mma.sync.aligned.m16n8k16.row.col.f32.bf16.bf16.f32 "
        "{%0,%1,%2,%3}, {%4,%5,%6,%7}, {%8,%9}, {%0,%1,%2,%3};"
        : "+f"(c[0]), "+f"(c[1]), "+f"(c[2]), "+f"(c[3])
        : "r"(a[0]), "r"(a[1]), "r"(a[2]), "r"(a[3]), "r"(b0), "r"(b1));
}
__device__ __forceinline__ uint32_t cvt2(float e1, float e0) {   // {hi=e1, lo=e0}
    uint32_t r;
    asm("cvt.rn.bf16x2.f32 %0, %1, %2;" : "=r"(r) : "f"(e1), "f"(e0));
    return r;
}
__device__ __forceinline__ void split2(float v0, float v1, uint32_t& hi, uint32_t& lo) {
    hi = cvt2(v1, v0);
    const float h0 = __uint_as_float(hi << 16);
    const float h1 = __uint_as_float(hi & 0xFFFF0000u);
    lo = cvt2(v1 - h1, v0 - h0);
}
__device__ __forceinline__ float silu_f(float h) {
    return __fdividef(h, 1.f + __expf(-h));
}

// ---------------- stage 1: per-sample partial sums --------------------------
__global__ void cp_stats_kernel(const float* __restrict__ z0) {
    const int b = blockIdx.y;
    const float4* z4 = (const float4*)(z0 + (size_t)b * CHW);
    const int n4 = CHW / 4;
    float s = 0.f, q = 0.f;
    for (int i = blockIdx.x * RED_THREADS + threadIdx.x; i < n4;
         i += RED_BLOCKS * RED_THREADS) {
        float4 v = z4[i];
        s += (v.x + v.y) + (v.z + v.w);
        q += (v.x * v.x + v.y * v.y) + (v.z * v.z + v.w * v.w);
    }
    #pragma unroll
    for (int off = 16; off; off >>= 1) {
        s += __shfl_down_sync(0xffffffffu, s, off);
        q += __shfl_down_sync(0xffffffffu, q, off);
    }
    __shared__ float ss[RED_THREADS / 32], sq[RED_THREADS / 32];
    const int w = threadIdx.x >> 5;
    if ((threadIdx.x & 31) == 0) { ss[w] = s; sq[w] = q; }
    __syncthreads();
    if (threadIdx.x == 0) {
        float S = 0.f, Q = 0.f;
        #pragma unroll
        for (int i = 0; i < RED_THREADS / 32; i++) { S += ss[i]; Q += sq[i]; }
        g_psum[b * RED_BLOCKS + blockIdx.x] = S;
        g_psq [b * RED_BLOCKS + blockIdx.x] = Q;
    }
}

// ---------------- stage 2: finalize + weight split/pad ----------------------
__global__ void cp_finalize_kernel(const float* __restrict__ w1,
                                   const float* __restrict__ w2) {
    const int t = threadIdx.x;   // 256
    if (t < NSAMP) {
        float S = 0.f, Q = 0.f;
        for (int i = 0; i < RED_BLOCKS; i++) {
            S += g_psum[t * RED_BLOCKS + i];
            Q += g_psq [t * RED_BLOCKS + i];
        }
        const float inv_n = 1.f / (float)CHW;
        const float mu  = S * inv_n;
        const float var = Q * inv_n - mu * mu;
        g_mu[t] = mu;
        g_rs[t] = rsqrtf(var + 1e-5f);
    }
    __nv_bfloat16* w1h = (__nv_bfloat16*)g_w1hi;
    __nv_bfloat16* w1l = (__nv_bfloat16*)g_w1lo;
    __nv_bfloat16* w2h = (__nv_bfloat16*)g_w2hi;
    __nv_bfloat16* w2l = (__nv_bfloat16*)g_w2lo;
    for (int i = t; i < 128 * 64; i += 256) {      // w1[h][k] -> [h][72]
        const int h = i >> 6, k = i & 63;
        const float v = w1[h * 64 + k];
        const __nv_bfloat16 hb = __float2bfloat16(v);
        w1h[h * 72 + k] = hb;
        w1l[h * 72 + k] = __float2bfloat16(v - __bfloat162float(hb));
    }
    for (int i = t; i < 64 * 128; i += 256) {      // w2[o][h] -> [o][136]
        const int o = i >> 7, h = i & 127;
        const float v = w2[o * 128 + h];
        const __nv_bfloat16 hb = __float2bfloat16(v);
        w2h[o * 136 + h] = hb;
        w2l[o * 136 + h] = __float2bfloat16(v - __bfloat162float(hb));
    }
}

// ---------------- stage 3: HMMA main kernel ---------------------------------
__global__ void __launch_bounds__(256, 1)
cp_main_kernel(const float* __restrict__ z0,
               const float* __restrict__ b1,
               const float* __restrict__ b2,
               float* __restrict__ out) {
    extern __shared__ char smc[];
    const uint32_t sb = smem_u32(smc);
    const int tid = threadIdx.x;
    const int w = tid >> 5, lane = tid & 31;
    const int g = lane >> 2, tig = lane & 3;
    const int lrow = lane & 15, lk = lane >> 4;          // ldsm.x4 lane mapping
    const int brow = lane & 7,  bk = (lane >> 3) & 1;    // ldsm.x2 lane mapping

    // ---- stage weights + biases ----
    for (int i = tid; i < 1152; i += 256) {
        ((uint4*)(smc + OFF_W1HI))[i] = g_w1hi[i];
        ((uint4*)(smc + OFF_W1LO))[i] = g_w1lo[i];
    }
    for (int i = tid; i < 1088; i += 256) {
        ((uint4*)(smc + OFF_W2HI))[i] = g_w2hi[i];
        ((uint4*)(smc + OFF_W2LO))[i] = g_w2lo[i];
    }
    float* b1s = (float*)(smc + OFF_B1);
    float* b2s = (float*)(smc + OFF_B2);
    if (tid < 128) b1s[tid] = b1[tid];
    if (tid < 64)  b2s[tid] = b2[tid];

    const int b = blockIdx.x / BLOCKS_PER_SAMPLE;
    const float* zb = z0 + (size_t)b * CHW;
    float*       ob = out + (size_t)b * CHW;
    const float mu = g_mu[b];
    const float rs = g_rs[b];
    float* stg = (float*)(smc + OFF_SHI);   // fp32 [c=64][px=128]

    for (int tl = 0; tl < TPB; tl++) {
        const int p0 = ((blockIdx.x % BLOCKS_PER_SAMPLE) * TPB + tl) * 128;
        __syncthreads();   // S/stg region free, weights staged

        // ---- staging: norm z1 -> stg ; z2 path -> out (both coalesced) ----
        for (int i = tid; i < 2048; i += 256) {       // 64ch x 32 float4
            const int c = i >> 5, f = (i & 31) * 4;
            float4 v = *(const float4*)(zb + (size_t)c * HW + p0 + f);
            v.x = (v.x - mu) * rs; v.y = (v.y - mu) * rs;
            v.z = (v.z - mu) * rs; v.w = (v.w - mu) * rs;
            *(float4*)(stg + c * 128 + f) = v;
            // z2: out[2c+1] = norm(z0[64+c]) + z0[2c+1]
            float4 zv = *(const float4*)(zb + (size_t)(CC + c) * HW + p0 + f);
            float4 rv = *(const float4*)(zb + (size_t)(2 * c + 1) * HW + p0 + f);
            float4 ov;
            ov.x = (zv.x - mu) * rs + rv.x; ov.y = (zv.y - mu) * rs + rv.y;
            ov.z = (zv.z - mu) * rs + rv.z; ov.w = (zv.w - mu) * rs + rv.w;
            *(float4*)(ob + (size_t)(2 * c + 1) * HW + p0 + f) = ov;
        }
        __syncthreads();

        // ---- stg -> A hi/lo bf16 [px][72] ----
        for (int i = tid; i < 1024; i += 256) {
            const int px = i & 127, c0 = (i >> 7) * 8;
            uint32_t hiw[4], low[4];
            #pragma unroll
            for (int j = 0; j < 4; j++)
                split2(stg[(c0 + 2 * j) * 128 + px], stg[(c0 + 2 * j + 1) * 128 + px],
                       hiw[j], low[j]);
            *(uint4*)(smc + OFF_AHI + px * 144 + c0 * 2) = make_uint4(hiw[0], hiw[1], hiw[2], hiw[3]);
            *(uint4*)(smc + OFF_ALO + px * 144 + c0 * 2) = make_uint4(low[0], low[1], low[2], low[3]);
        }
        __syncthreads();

        // ---- GEMM1: [16px x 128h] per warp, K=64, 3 split passes ----
        float acc[16][4];
        #pragma unroll
        for (int nt = 0; nt < 16; nt++)
            #pragma unroll
            for (int i = 0; i < 4; i++) acc[nt][i] = 0.f;
        #pragma unroll
        for (int ks = 0; ks < 4; ks++) {
            uint32_t aH[4], aL[4];
            const uint32_t ad = sb + OFF_AHI + (w * 16 + lrow) * 144 + (ks * 16 + lk * 8) * 2;
            ldsm_x4(aH, ad);
            ldsm_x4(aL, ad + (OFF_ALO - OFF_AHI));
            #pragma unroll
            for (int nt = 0; nt < 16; nt++) {
                const uint32_t bd = sb + OFF_W1HI + (nt * 8 + brow) * 144 + (ks * 16 + bk * 8) * 2;
                uint32_t bh0, bh1, bl0, bl1;
                ldsm_x2(bh0, bh1, bd);
                ldsm_x2(bl0, bl1, bd + (OFF_W1LO - OFF_W1HI));
                mma_bf16(acc[nt], aH, bh0, bh1);
                mma_bf16(acc[nt], aL, bh0, bh1);
                mma_bf16(acc[nt], aH, bl0, bl1);
            }
        }
        // ---- SiLU(+b1) -> S hi/lo [px][136] ----
        #pragma unroll
        for (int nt = 0; nt < 16; nt++) {
            const int h0 = nt * 8 + 2 * tig;
            const float bi0 = b1s[h0], bi1 = b1s[h0 + 1];
            const float v0 = silu_f(acc[nt][0] + bi0), v1 = silu_f(acc[nt][1] + bi1);
            const float v2 = silu_f(acc[nt][2] + bi0), v3 = silu_f(acc[nt][3] + bi1);
            uint32_t h01, l01, h23, l23;
            split2(v0, v1, h01, l01);
            split2(v2, v3, h23, l23);
            const uint32_t r0 = (w * 16 + g) * 272 + h0 * 2;
            const uint32_t r1 = (w * 16 + g + 8) * 272 + h0 * 2;
            *(uint32_t*)(smc + OFF_SHI + r0) = h01;
            *(uint32_t*)(smc + OFF_SLO + r0) = l01;
            *(uint32_t*)(smc + OFF_SHI + r1) = h23;
            *(uint32_t*)(smc + OFF_SLO + r1) = l23;
        }
        __syncwarp();   // warp reads only its own S rows

        // ---- GEMM2: [16px x 64o] per warp, K=128, 3 split passes ----
        float acc2[8][4];
        #pragma unroll
        for (int nt = 0; nt < 8; nt++)
            #pragma unroll
            for (int i = 0; i < 4; i++) acc2[nt][i] = 0.f;
        #pragma unroll
        for (int ks = 0; ks < 8; ks++) {
            uint32_t aH[4], aL[4];
            const uint32_t ad = sb + OFF_SHI + (w * 16 + lrow) * 272 + (ks * 16 + lk * 8) * 2;
            ldsm_x4(aH, ad);
            ldsm_x4(aL, ad + (OFF_SLO - OFF_SHI));
            #pragma unroll
            for (int nt = 0; nt < 8; nt++) {
                const uint32_t bd = sb + OFF_W2HI + (nt * 8 + brow) * 272 + (ks * 16 + bk * 8) * 2;
                uint32_t bh0, bh1, bl0, bl1;
                ldsm_x2(bh0, bh1, bd);
                ldsm_x2(bl0, bl1, bd + (OFF_W2LO - OFF_W2HI));
                mma_bf16(acc2[nt], aH, bh0, bh1);
                mma_bf16(acc2[nt], aL, bh0, bh1);
                mma_bf16(acc2[nt], aH, bl0, bl1);
            }
        }
        // ---- epilogue: out[2o] = y + b2 + z0[2o] (channel shuffle + resid) ----
        const int pxl = p0 + w * 16 + g;
        #pragma unroll
        for (int nt = 0; nt < 8; nt++) {
            const int o0 = nt * 8 + 2 * tig;
            const size_t r0 = (size_t)(2 * o0) * HW;
            const size_t r1 = (size_t)(2 * o0 + 2) * HW;
            ob[r0 + pxl]     = acc2[nt][0] + b2s[o0]     + zb[r0 + pxl];
            ob[r1 + pxl]     = acc2[nt][1] + b2s[o0 + 1] + zb[r1 + pxl];
            ob[r0 + pxl + 8] = acc2[nt][2] + b2s[o0]     + zb[r0 + pxl + 8];
            ob[r1 + pxl + 8] = acc2[nt][3] + b2s[o0 + 1] + zb[r1 + pxl + 8];
        }
    }
}

// ---------------------------------------------------------------------------
extern "C" void kernel_launch(void* const* d_in, const int* in_sizes, int n_in,
                              void* d_out, int out_size) {
    const float* z0 = (const float*)d_in[0];
    const float* w1 = (const float*)d_in[1];
    const float* b1 = (const float*)d_in[2];
    const float* w2 = (const float*)d_in[3];
    const float* b2 = (const float*)d_in[4];
    float* out = (float*)d_out;

    static bool attr_set = false;
    if (!attr_set) {
        cudaFuncSetAttribute(cp_main_kernel,
                             cudaFuncAttributeMaxDynamicSharedMemorySize,
                             SMEM_MAIN);
        attr_set = true;
    }

    cp_stats_kernel<<<dim3(RED_BLOCKS, NSAMP), RED_THREADS>>>(z0);
    cp_finalize_kernel<<<1, 256>>>(w1, w2);
    cp_main_kernel<<<MAIN_GRID, 256, SMEM_MAIN>>>(z0, b1, b2, out);
}

// round 8
// speedup vs baseline: 3.9195x; 1.3801x over previous
#include <cuda_runtime.h>
#include <cuda_fp16.h>
#include <cstdint>

// ---------------------------------------------------------------------------
// ChannelProjection via mma.sync (HMMA fp16, base-target ISA).
// fp16-split 2-pass: D = (A_hi + A_lo) x B_fp16  (dropped term ~2^-11 rel).
// 64-px tiles, 88KB smem -> 2 CTAs/SM (phase overlap across CTAs).
//   k1: per-sample sum/sumsq reduction
//   k2: finalize mu/rsigma + fp16 weights (padded strides)
//   k3: per 64-px tile: stage norm z1, split A hi/lo, GEMM1 (2-pass) -> SiLU
//       -> S hi/lo, GEMM2 (2-pass) -> epilogue (shuffle + residual).
// ---------------------------------------------------------------------------

#define C_TOT   128
#define CC      64
#define HW      36864
#define NSAMP   16
#define CHW     (C_TOT * HW)
#define NPIX    (NSAMP * HW)
#define RED_BLOCKS  64
#define RED_THREADS 256

#define TPB       8
#define BLOCKS_PER_SAMPLE 72            // 72 * 8 * 64 = 36864 px
#define MAIN_GRID (NSAMP * BLOCKS_PER_SAMPLE)   // 1152

// smem offsets; strides: A/W1 rows 144B (72 fp16), S/W2 rows 272B (136 fp16)
#define OFF_W1    0          // [128h][72k]   18432
#define OFF_W2    18432      // [64o][136h]   17408
#define OFF_AHI   35840      // [64px][72k]    9216
#define OFF_ALO   45056
#define OFF_SHI   54272      // [64px][136h]  17408 (fp32 stg [64c][64px] aliases)
#define OFF_SLO   71680
#define OFF_B1    89088      // 128 f32
#define OFF_B2    89600      // 64 f32
#define SMEM_MAIN 89856

__device__ float g_psum[NSAMP * RED_BLOCKS];
__device__ float g_psq [NSAMP * RED_BLOCKS];
__device__ float g_mu  [NSAMP];
__device__ float g_rs  [NSAMP];
__device__ uint4 g_w1h[1152];   // 128*72 fp16
__device__ uint4 g_w2h[1088];   // 64*136 fp16

// ---------------- helpers ---------------------------------------------------
__device__ __forceinline__ uint32_t smem_u32(const void* p) {
    uint32_t a;
    asm("{ .reg .u64 t; cvta.to.shared.u64 t, %1; cvt.u32.u64 %0, t; }"
        : "=r"(a) : "l"(p));
    return a;
}
__device__ __forceinline__ void ldsm_x4(uint32_t (&r)[4], uint32_t addr) {
    asm volatile("ldmatrix.sync.aligned.m8n8.x4.shared.b16 {%0,%1,%2,%3}, [%4];"
                 : "=r"(r[0]), "=r"(r[1]), "=r"(r[2]), "=r"(r[3]) : "r"(addr));
}
__device__ __forceinline__ void ldsm_x2(uint32_t& r0, uint32_t& r1, uint32_t addr) {
    asm volatile("ldmatrix.sync.aligned.m8n8.x2.shared.b16 {%0,%1}, [%2];"
                 : "=r"(r0), "=r"(r1) : "r"(addr));
}
__device__ __forceinline__ void mma_f16(float (&c)[4], const uint32_t (&a)[4],
                                        uint32_t b0, uint32_t b1) {
    asm volatile(
        "mma.sync.aligned.m16n8k16.row.col.f32.f16.f16.f32 "
        "{%0,%1,%2,%3}, {%4,%5,%6,%7}, {%8,%9}, {%0,%1,%2,%3};"
        : "+f"(c[0]), "+f"(c[1]), "+f"(c[2]), "+f"(c[3])
        : "r"(a[0]), "r"(a[1]), "r"(a[2]), "r"(a[3]), "r"(b0), "r"(b1));
}
__device__ __forceinline__ uint32_t packh(__half a, __half b) {
    __half2 h; h.x = a; h.y = b;
    return *(uint32_t*)&h;
}
// split pair (v0,v1) into fp16 hi word + fp16 lo (residual) word
__device__ __forceinline__ void split2h(float v0, float v1, uint32_t& hi, uint32_t& lo) {
    const __half h0 = __float2half_rn(v0);
    const __half h1 = __float2half_rn(v1);
    const __half l0 = __float2half_rn(v0 - __half2float(h0));
    const __half l1 = __float2half_rn(v1 - __half2float(h1));
    hi = packh(h0, h1);
    lo = packh(l0, l1);
}
__device__ __forceinline__ float silu_f(float h) {
    return __fdividef(h, 1.f + __expf(-h));
}

// ---------------- stage 1: per-sample partial sums --------------------------
__global__ void cp_stats_kernel(const float* __restrict__ z0) {
    const int b = blockIdx.y;
    const float4* z4 = (const float4*)(z0 + (size_t)b * CHW);
    const int n4 = CHW / 4;
    float s = 0.f, q = 0.f;
    for (int i = blockIdx.x * RED_THREADS + threadIdx.x; i < n4;
         i += RED_BLOCKS * RED_THREADS) {
        float4 v = z4[i];
        s += (v.x + v.y) + (v.z + v.w);
        q += (v.x * v.x + v.y * v.y) + (v.z * v.z + v.w * v.w);
    }
    #pragma unroll
    for (int off = 16; off; off >>= 1) {
        s += __shfl_down_sync(0xffffffffu, s, off);
        q += __shfl_down_sync(0xffffffffu, q, off);
    }
    __shared__ float ss[RED_THREADS / 32], sq[RED_THREADS / 32];
    const int w = threadIdx.x >> 5;
    if ((threadIdx.x & 31) == 0) { ss[w] = s; sq[w] = q; }
    __syncthreads();
    if (threadIdx.x == 0) {
        float S = 0.f, Q = 0.f;
        #pragma unroll
        for (int i = 0; i < RED_THREADS / 32; i++) { S += ss[i]; Q += sq[i]; }
        g_psum[b * RED_BLOCKS + blockIdx.x] = S;
        g_psq [b * RED_BLOCKS + blockIdx.x] = Q;
    }
}

// ---------------- stage 2: finalize + fp16 weights --------------------------
__global__ void cp_finalize_kernel(const float* __restrict__ w1,
                                   const float* __restrict__ w2) {
    const int t = threadIdx.x;   // 256
    if (t < NSAMP) {
        float S = 0.f, Q = 0.f;
        for (int i = 0; i < RED_BLOCKS; i++) {
            S += g_psum[t * RED_BLOCKS + i];
            Q += g_psq [t * RED_BLOCKS + i];
        }
        const float inv_n = 1.f / (float)CHW;
        const float mu  = S * inv_n;
        const float var = Q * inv_n - mu * mu;
        g_mu[t] = mu;
        g_rs[t] = rsqrtf(var + 1e-5f);
    }
    __half* w1h = (__half*)g_w1h;
    __half* w2h = (__half*)g_w2h;
    for (int i = t; i < 128 * 64; i += 256) {      // w1[h][k] -> [h][72]
        const int h = i >> 6, k = i & 63;
        w1h[h * 72 + k] = __float2half_rn(w1[h * 64 + k]);
    }
    for (int i = t; i < 64 * 128; i += 256) {      // w2[o][h] -> [o][136]
        const int o = i >> 7, h = i & 127;
        w2h[o * 136 + h] = __float2half_rn(w2[o * 128 + h]);
    }
}

// ---------------- stage 3: HMMA main kernel (2 CTAs/SM) ---------------------
__global__ void __launch_bounds__(256, 2)
cp_main_kernel(const float* __restrict__ z0,
               const float* __restrict__ b1,
               const float* __restrict__ b2,
               float* __restrict__ out) {
    extern __shared__ char smc[];
    const uint32_t sb = smem_u32(smc);
    const int tid = threadIdx.x;
    const int w = tid >> 5, lane = tid & 31;
    const int g = lane >> 2, tig = lane & 3;
    const int lrow = lane & 15, lk = lane >> 4;          // ldsm.x4 mapping
    const int brow = lane & 7,  bk = (lane >> 3) & 1;    // ldsm.x2 mapping
    const int pg = w & 3;          // pixel group (16 px)
    const int hh = w >> 2;         // h-half (GEMM1) / o-half (GEMM2)

    // ---- stage weights + biases ----
    for (int i = tid; i < 1152; i += 256) ((uint4*)(smc + OFF_W1))[i] = g_w1h[i];
    for (int i = tid; i < 1088; i += 256) ((uint4*)(smc + OFF_W2))[i] = g_w2h[i];
    float* b1s = (float*)(smc + OFF_B1);
    float* b2s = (float*)(smc + OFF_B2);
    if (tid < 128) b1s[tid] = b1[tid];
    if (tid < 64)  b2s[tid] = b2[tid];

    const int b = blockIdx.x / BLOCKS_PER_SAMPLE;
    const float* zb = z0 + (size_t)b * CHW;
    float*       ob = out + (size_t)b * CHW;
    const float mu = g_mu[b];
    const float rs = g_rs[b];
    float* stg = (float*)(smc + OFF_SHI);   // fp32 [c=64][px=64] aliases S_hi

    for (int tl = 0; tl < TPB; tl++) {
        const int p0 = ((blockIdx.x % BLOCKS_PER_SAMPLE) * TPB + tl) * 64;
        __syncthreads();   // S/stg free (prev tile GEMM2 done), weights staged

        // ---- staging: norm z1 -> stg ; z2 path -> out (coalesced) ----
        for (int i = tid; i < 1024; i += 256) {       // 64ch x 16 float4
            const int c = i >> 4, f = (i & 15) * 4;
            float4 v = *(const float4*)(zb + (size_t)c * HW + p0 + f);
            v.x = (v.x - mu) * rs; v.y = (v.y - mu) * rs;
            v.z = (v.z - mu) * rs; v.w = (v.w - mu) * rs;
            *(float4*)(stg + c * 64 + f) = v;
            float4 zv = *(const float4*)(zb + (size_t)(CC + c) * HW + p0 + f);
            float4 rv = *(const float4*)(zb + (size_t)(2 * c + 1) * HW + p0 + f);
            float4 ov;
            ov.x = (zv.x - mu) * rs + rv.x; ov.y = (zv.y - mu) * rs + rv.y;
            ov.z = (zv.z - mu) * rs + rv.z; ov.w = (zv.w - mu) * rs + rv.w;
            *(float4*)(ob + (size_t)(2 * c + 1) * HW + p0 + f) = ov;
        }
        __syncthreads();

        // ---- stg -> A hi/lo fp16 [px][72] ----
        for (int i = tid; i < 512; i += 256) {
            const int px = i & 63, c0 = (i >> 6) * 8;
            uint32_t hiw[4], low[4];
            #pragma unroll
            for (int j = 0; j < 4; j++)
                split2h(stg[(c0 + 2 * j) * 64 + px], stg[(c0 + 2 * j + 1) * 64 + px],
                        hiw[j], low[j]);
            *(uint4*)(smc + OFF_AHI + px * 144 + c0 * 2) = make_uint4(hiw[0], hiw[1], hiw[2], hiw[3]);
            *(uint4*)(smc + OFF_ALO + px * 144 + c0 * 2) = make_uint4(low[0], low[1], low[2], low[3]);
        }
        __syncthreads();

        // ---- GEMM1: [16px x 64h] per warp, K=64, 2 split passes ----
        float acc[8][4];
        #pragma unroll
        for (int nt = 0; nt < 8; nt++)
            #pragma unroll
            for (int i = 0; i < 4; i++) acc[nt][i] = 0.f;
        #pragma unroll
        for (int ks = 0; ks < 4; ks++) {
            uint32_t aH[4], aL[4];
            const uint32_t ad = sb + OFF_AHI + (pg * 16 + lrow) * 144 + (ks * 16 + lk * 8) * 2;
            ldsm_x4(aH, ad);
            ldsm_x4(aL, ad + (OFF_ALO - OFF_AHI));
            #pragma unroll
            for (int nt = 0; nt < 8; nt++) {
                const uint32_t bd = sb + OFF_W1 + (hh * 64 + nt * 8 + brow) * 144
                                  + (ks * 16 + bk * 8) * 2;
                uint32_t b0, b1r;
                ldsm_x2(b0, b1r, bd);
                mma_f16(acc[nt], aH, b0, b1r);
                mma_f16(acc[nt], aL, b0, b1r);
            }
        }
        // ---- SiLU(+b1) -> S hi/lo [px][136] ----
        #pragma unroll
        for (int nt = 0; nt < 8; nt++) {
            const int h0 = hh * 64 + nt * 8 + 2 * tig;
            const float bi0 = b1s[h0], bi1 = b1s[h0 + 1];
            const float v0 = silu_f(acc[nt][0] + bi0), v1 = silu_f(acc[nt][1] + bi1);
            const float v2 = silu_f(acc[nt][2] + bi0), v3 = silu_f(acc[nt][3] + bi1);
            uint32_t h01, l01, h23, l23;
            split2h(v0, v1, h01, l01);
            split2h(v2, v3, h23, l23);
            const uint32_t r0 = (pg * 16 + g) * 272 + h0 * 2;
            const uint32_t r1 = (pg * 16 + g + 8) * 272 + h0 * 2;
            *(uint32_t*)(smc + OFF_SHI + r0) = h01;
            *(uint32_t*)(smc + OFF_SLO + r0) = l01;
            *(uint32_t*)(smc + OFF_SHI + r1) = h23;
            *(uint32_t*)(smc + OFF_SLO + r1) = l23;
        }
        __syncthreads();   // S rows get contributions from both h-half warps

        // ---- GEMM2: [16px x 32o] per warp, K=128, 2 split passes ----
        float acc2[4][4];
        #pragma unroll
        for (int nt = 0; nt < 4; nt++)
            #pragma unroll
            for (int i = 0; i < 4; i++) acc2[nt][i] = 0.f;
        #pragma unroll
        for (int ks = 0; ks < 8; ks++) {
            uint32_t aH[4], aL[4];
            const uint32_t ad = sb + OFF_SHI + (pg * 16 + lrow) * 272 + (ks * 16 + lk * 8) * 2;
            ldsm_x4(aH, ad);
            ldsm_x4(aL, ad + (OFF_SLO - OFF_SHI));
            #pragma unroll
            for (int nt = 0; nt < 4; nt++) {
                const uint32_t bd = sb + OFF_W2 + (hh * 32 + nt * 8 + brow) * 272
                                  + (ks * 16 + bk * 8) * 2;
                uint32_t b0, b1r;
                ldsm_x2(b0, b1r, bd);
                mma_f16(acc2[nt], aH, b0, b1r);
                mma_f16(acc2[nt], aL, b0, b1r);
            }
        }
        // ---- epilogue: out[2o] = y + b2 + z0[2o] ----
        const int pxl = p0 + pg * 16 + g;
        #pragma unroll
        for (int nt = 0; nt < 4; nt++) {
            const int o0 = hh * 32 + nt * 8 + 2 * tig;
            const size_t r0 = (size_t)(2 * o0) * HW;
            const size_t r1 = (size_t)(2 * o0 + 2) * HW;
            ob[r0 + pxl]     = acc2[nt][0] + b2s[o0]     + zb[r0 + pxl];
            ob[r1 + pxl]     = acc2[nt][1] + b2s[o0 + 1] + zb[r1 + pxl];
            ob[r0 + pxl + 8] = acc2[nt][2] + b2s[o0]     + zb[r0 + pxl + 8];
            ob[r1 + pxl + 8] = acc2[nt][3] + b2s[o0 + 1] + zb[r1 + pxl + 8];
        }
    }
}

// ---------------------------------------------------------------------------
extern "C" void kernel_launch(void* const* d_in, const int* in_sizes, int n_in,
                              void* d_out, int out_size) {
    const float* z0 = (const float*)d_in[0];
    const float* w1 = (const float*)d_in[1];
    const float* b1 = (const float*)d_in[2];
    const float* w2 = (const float*)d_in[3];
    const float* b2 = (const float*)d_in[4];
    float* out = (float*)d_out;

    static bool attr_set = false;
    if (!attr_set) {
        cudaFuncSetAttribute(cp_main_kernel,
                             cudaFuncAttributeMaxDynamicSharedMemorySize,
                             SMEM_MAIN);
        attr_set = true;
    }

    cp_stats_kernel<<<dim3(RED_BLOCKS, NSAMP), RED_THREADS>>>(z0);
    cp_finalize_kernel<<<1, 256>>>(w1, w2);
    cp_main_kernel<<<MAIN_GRID, 256, SMEM_MAIN>>>(z0, b1, b2, out);
}